// round 5
// baseline (speedup 1.0000x reference)
#include <cuda_runtime.h>
#include <math.h>

#define BB 16
#define LL 128
#define HH 100
#define H2 200
#define PP 20
#define CC 210
#define EPSF 1e-8f
#define TS 129   // transposed tile row stride (odd -> conflict-free)

typedef unsigned long long u64;

__device__ __forceinline__ u64 mul2(u64 a, u64 b) {
    u64 d; asm("mul.rn.f32x2 %0,%1,%2;" : "=l"(d) : "l"(a), "l"(b)); return d;
}
__device__ __forceinline__ void fma2(u64& d, u64 a, u64 b) {
    asm("fma.rn.f32x2 %0,%1,%2,%0;" : "+l"(d) : "l"(a), "l"(b));
}
__device__ __forceinline__ float2 up2(u64 x) {
    float2 r; asm("mov.b64 {%0,%1}, %2;" : "=f"(r.x), "=f"(r.y) : "l"(x)); return r;
}

// ---------------- scratch ----------------
__device__ float g_norm[4][BB][LL];
__device__ float g_wnorm[4][4][BB][PP][LL];
__device__ __align__(16) float g_att[8][BB][LL][HH];
__device__ __align__(16) float g_cos[2][BB][LL][LL];   // [dir][b][i][j]
__device__ int   g_last[2][BB];
__device__ __align__(16) float g_hp[2][BB][16][LL][2*PP];

// ---------------- K1: norms (+ last indices, folded-in k0) ----------------
__global__ void __launch_bounds__(128) k1_norms(const float* __restrict__ cp,
                                                const float* __restrict__ ch,
                                                const float* __restrict__ params,
                                                const int* __restrict__ mp,
                                                const int* __restrict__ mh)
{
    int b = blockIdx.y, i0 = blockIdx.x * 8, tid = threadIdx.x;
    __shared__ float vsq[8][4][HH];
    for (int t = tid; t < 8 * 2 * H2; t += 128) {
        int a = t / (2 * H2);
        int rem = t % (2 * H2);
        float v;
        if (rem < H2) v = cp[((size_t)b*LL + i0 + a)*H2 + rem];
        else          v = ch[((size_t)b*LL + i0 + a)*H2 + rem - H2];
        vsq[a][rem / HH][rem % HH] = v * v;
    }
    __syncthreads();
    if (tid < 32) {
        int a = tid >> 2, r = tid & 3;
        float s = 0.f;
        for (int h = 0; h < HH; h++) s += vsq[a][r][h];
        g_norm[r][b][i0 + a] = sqrtf(s);
    }
    for (int t = tid; t < 4 * 4 * PP; t += 128) {
        int r = t / (4 * PP);
        int rem = t % (4 * PP);
        int ml = rem / PP, p = rem % PP;
        int m = (r & 1) ? (2 * ml + 1) : (2 * ml);
        const float* w = params + (m * PP + p) * HH;
        float s[8] = {0,0,0,0,0,0,0,0};
        for (int h = 0; h < HH; h++) {
            float wv = w[h]; float w2 = wv * wv;
            #pragma unroll
            for (int a = 0; a < 8; a++) s[a] += w2 * vsq[a][r][h];
        }
        #pragma unroll
        for (int a = 0; a < 8; a++) g_wnorm[r][ml][b][p][i0 + a] = sqrtf(s[a]);
    }
    if (blockIdx.x == 0 && blockIdx.y == 0 && tid < BB) {
        int lp = 0, lh = 0;
        for (int j = 0; j < LL; j++) { lp += mp[tid*LL + j]; lh += mh[tid*LL + j]; }
        g_last[0][tid] = max(lp - 1, 0);
        g_last[1][tid] = max(lh - 1, 0);
    }
}

// ---------------- K23: cos + row stats + attentive h vectors (8 anchors, 1 dir/block) ----
// dyn smem: tile[100][TS]@0 (12900), pan[8*100]@12900, cosr[8*128]@13700, stat[8*2]@14724
__global__ void __launch_bounds__(128) k23_rows(const float* __restrict__ cp,
                                                const float* __restrict__ ch,
                                                float* __restrict__ outp)
{
    extern __shared__ float sm[];
    float* tile = sm;
    float* pan  = sm + 12900;
    float* cosr = sm + 13700;
    float* stat = sm + 14724;

    int b = blockIdx.y, i0 = blockIdx.x * 8, dir = blockIdx.z, tid = threadIdx.x;

    // stage ch dir-slice transposed: tile[h][j]
    {
        const float* tb = ch + (size_t)b*LL*H2 + dir*HH;
        for (int t = tid; t < 128 * 25; t += 128) {
            int j = t / 25, c = t % 25;
            float4 v = *(const float4*)(tb + (size_t)j*H2 + 4*c);
            tile[(4*c + 0)*TS + j] = v.x;
            tile[(4*c + 1)*TS + j] = v.y;
            tile[(4*c + 2)*TS + j] = v.z;
            tile[(4*c + 3)*TS + j] = v.w;
        }
        const float* pb = cp + ((size_t)b*LL + i0)*H2 + dir*HH;
        for (int t = tid; t < 8 * 25; t += 128) {
            int a = t / 25, c = t % 25;
            *(float4*)(pan + a*HH + 4*c) = *(const float4*)(pb + (size_t)a*H2 + 4*c);
        }
    }
    __syncthreads();

    // cos for this thread's j over 8 anchors
    {
        int j = tid;
        float nj = g_norm[2 + dir][b][j];
        float dacc[8];
        #pragma unroll
        for (int a = 0; a < 8; a++) dacc[a] = 0.f;
        for (int h = 0; h < HH; h += 2) {
            float v0 = tile[h*TS + j];
            float v1 = tile[(h+1)*TS + j];
            #pragma unroll
            for (int a = 0; a < 8; a++) {
                float2 w = *(const float2*)&pan[a*HH + h];
                dacc[a] += v0 * w.x;
                dacc[a] += v1 * w.y;
            }
        }
        #pragma unroll
        for (int a = 0; a < 8; a++) {
            float ni = g_norm[dir][b][i0 + a];
            float cv = dacc[a] / fmaxf(ni * nj, EPSF);
            cosr[a*128 + j] = cv;
            g_cos[dir][b][i0 + a][j] = cv;
        }
    }
    __syncthreads();

    int w = tid >> 5, lane = tid & 31;
    for (int a = w; a < 8; a += 4) {
        float mx = -INFINITY, s = 0.f;
        for (int jj = lane; jj < 128; jj += 32) {
            float v = cosr[a*128 + jj];
            mx = fmaxf(mx, v); s += v;
        }
        #pragma unroll
        for (int o = 16; o; o >>= 1) {
            mx = fmaxf(mx, __shfl_xor_sync(0xffffffffu, mx, o));
            s += __shfl_xor_sync(0xffffffffu, s, o);
        }
        if (lane == 0) { stat[a*2] = mx; stat[a*2 + 1] = s; }
    }
    __syncthreads();

    if (tid < 8) {
        float* o = outp + ((size_t)b*LL + i0 + tid)*CC;
        o[2*dir]     = stat[tid*2];
        o[2*dir + 1] = stat[tid*2 + 1] * (1.f/LL);
    }

    if (tid < HH) {
        int h = tid;
        float inv[8], smv[8], mxv[8];
        #pragma unroll
        for (int a = 0; a < 8; a++) {
            inv[a] = 1.f / fmaxf(stat[a*2 + 1], EPSF);
            smv[a] = 0.f; mxv[a] = -INFINITY;
        }
        const float* trow = tile + h*TS;
        for (int jj = 0; jj < 128; jj += 2) {
            float hv0 = trow[jj];
            float hv1 = trow[jj + 1];
            #pragma unroll
            for (int a = 0; a < 8; a++) {
                float2 c2 = *(const float2*)&cosr[a*128 + jj];
                float v0 = c2.x * hv0, v1 = c2.y * hv1;
                smv[a] += v0; smv[a] += v1;
                mxv[a] = fmaxf(mxv[a], fmaxf(v0, v1));
            }
        }
        #pragma unroll
        for (int a = 0; a < 8; a++) {
            g_att[dir][b][i0 + a][h]     = smv[a] * inv[a];
            g_att[4 + dir][b][i0 + a][h] = mxv[a];
        }
    }
}

// ---------------- K4: col stats + attentive p vectors (8 j-anchors, 1 dir/block) ----
// dyn smem: tile[100][TS]@0 (12900), cosc[8*128]@12900, stat[8*2]@13924
__global__ void __launch_bounds__(128) k4_cols(const float* __restrict__ cp,
                                               float* __restrict__ outh)
{
    extern __shared__ float sm[];
    float* tile = sm;
    float* cosc = sm + 12900;
    float* stat = sm + 13924;

    int b = blockIdx.y, j0 = blockIdx.x * 8, dir = blockIdx.z, tid = threadIdx.x;

    {
        const float* tb = cp + (size_t)b*LL*H2 + dir*HH;
        for (int t = tid; t < 128 * 25; t += 128) {
            int i = t / 25, c = t % 25;
            float4 v = *(const float4*)(tb + (size_t)i*H2 + 4*c);
            tile[(4*c + 0)*TS + i] = v.x;
            tile[(4*c + 1)*TS + i] = v.y;
            tile[(4*c + 2)*TS + i] = v.z;
            tile[(4*c + 3)*TS + i] = v.w;
        }
        for (int t = tid; t < 128 * 2; t += 128) {
            int i = t >> 1, q = t & 1;
            float4 v = *(const float4*)&g_cos[dir][b][i][j0 + 4*q];
            cosc[(4*q + 0)*128 + i] = v.x;
            cosc[(4*q + 1)*128 + i] = v.y;
            cosc[(4*q + 2)*128 + i] = v.z;
            cosc[(4*q + 3)*128 + i] = v.w;
        }
    }
    __syncthreads();

    int w = tid >> 5, lane = tid & 31;
    for (int a = w; a < 8; a += 4) {
        float mx = -INFINITY, s = 0.f;
        for (int ii = lane; ii < 128; ii += 32) {
            float v = cosc[a*128 + ii];
            mx = fmaxf(mx, v); s += v;
        }
        #pragma unroll
        for (int o = 16; o; o >>= 1) {
            mx = fmaxf(mx, __shfl_xor_sync(0xffffffffu, mx, o));
            s += __shfl_xor_sync(0xffffffffu, s, o);
        }
        if (lane == 0) { stat[a*2] = mx; stat[a*2 + 1] = s; }
    }
    __syncthreads();

    if (tid < 8) {
        float* o = outh + ((size_t)b*LL + j0 + tid)*CC;
        o[2*dir]     = stat[tid*2];
        o[2*dir + 1] = stat[tid*2 + 1] * (1.f/LL);
    }

    if (tid < HH) {
        int h = tid;
        float inv[8], smv[8], mxv[8];
        #pragma unroll
        for (int a = 0; a < 8; a++) {
            inv[a] = 1.f / fmaxf(stat[a*2 + 1], EPSF);
            smv[a] = 0.f; mxv[a] = -INFINITY;
        }
        const float* trow = tile + h*TS;
        for (int ii = 0; ii < 128; ii += 2) {
            float pv0 = trow[ii];
            float pv1 = trow[ii + 1];
            #pragma unroll
            for (int a = 0; a < 8; a++) {
                float2 c2 = *(const float2*)&cosc[a*128 + ii];
                float v0 = c2.x * pv0, v1 = c2.y * pv1;
                smv[a] += v0; smv[a] += v1;
                mxv[a] = fmaxf(mxv[a], fmaxf(v0, v1));
            }
        }
        #pragma unroll
        for (int a = 0; a < 8; a++) {
            g_att[2 + dir][b][j0 + a][h] = smv[a] * inv[a];
            g_att[6 + dir][b][j0 + a][h] = mxv[a];
        }
    }
}

// ---------------- K5: vector-mpm groups ----------------
__global__ void __launch_bounds__(128) k5_vec(const float* __restrict__ cp,
                                              const float* __restrict__ ch,
                                              const float* __restrict__ params,
                                              float* __restrict__ out)
{
    int b = blockIdx.y, side = blockIdx.z, i0 = blockIdx.x * 4, tid = threadIdx.x;
    __shared__ __align__(16) float v1s[4][2][HH];
    __shared__ __align__(16) float v2f[2][HH];
    __shared__ __align__(16) float v2a[4][4][HH];
    const float* base1 = side == 0 ? cp : ch;
    const float* other = side == 0 ? ch : cp;
    for (int t = tid; t < 4 * H2; t += 128) {
        int a = t / H2, rem = t % H2;
        v1s[a][rem / HH][rem % HH] = base1[((size_t)b*LL + i0 + a)*H2 + rem];
    }
    int lastIdx = g_last[side == 0 ? 1 : 0][b];
    for (int t = tid; t < H2; t += 128) {
        if (t < HH) v2f[0][t] = other[((size_t)b*LL + lastIdx)*H2 + t];
        else        v2f[1][t - HH] = other[(size_t)b*LL*H2 + t];
    }
    int a0 = side == 0 ? 0 : 2, a4 = side == 0 ? 4 : 6;
    for (int t = tid; t < 4 * 4 * HH; t += 128) {
        int a = t / (4 * HH);
        int g = (t / HH) % 4;
        int h = t % HH;
        int att = (g < 2) ? (a0 + g) : (a4 + g - 2);
        v2a[a][g][h] = g_att[att][b][i0 + a][h];
    }
    __syncthreads();
    if (tid < 120) {
        int g = tid / PP, p = tid % PP;
        const int mtab[6] = {0, 1, 4, 5, 6, 7};
        const int btab[6] = {4, 25, 126, 147, 168, 189};
        int m = mtab[g], dir = g & 1, base = btab[g];
        int rowset = side * 2 + dir;
        const float4* w4 = (const float4*)(params + (m * PP + p) * HH);
        for (int a = 0; a < 4; a++) {
            const float4* v14 = (const float4*)v1s[a][dir];
            const float4* v24 = (g == 0) ? (const float4*)v2f[0]
                               : (g == 1) ? (const float4*)v2f[1]
                                          : (const float4*)v2a[a][g - 2];
            float s12 = 0.f, s22 = 0.f;
            #pragma unroll 5
            for (int c = 0; c < 25; c++) {
                float4 w = w4[c], x = v24[c], v1 = v14[c];
                float w2x = w.x*w.x, w2y = w.y*w.y, w2z = w.z*w.z, w2w = w.w*w.w;
                s12 += w2x*v1.x*x.x + w2y*v1.y*x.y + w2z*v1.z*x.z + w2w*v1.w*x.w;
                s22 += w2x*x.x*x.x + w2y*x.y*x.y + w2z*x.z*x.z + w2w*x.w*x.w;
            }
            float n1 = g_wnorm[rowset][m >> 1][b][p][i0 + a];
            float val = s12 / (fmaxf(n1, EPSF) * fmaxf(sqrtf(s22), EPSF));
            float* o = out + ((size_t)side*BB*LL + (size_t)b*LL + i0 + a)*CC;
            o[base + 1 + p] = val;
            if (p == 0) {
                float d = 0.f, q = 0.f;
                #pragma unroll 5
                for (int c = 0; c < 25; c++) {
                    float4 x = v24[c], v1 = v14[c];
                    d += v1.x*x.x + v1.y*x.y + v1.z*x.z + v1.w*x.w;
                    q += x.x*x.x + x.y*x.y + x.z*x.z + x.w*x.w;
                }
                float pn = g_norm[rowset][b][i0 + a];
                o[base] = d / (fmaxf(pn, EPSF) * fmaxf(sqrtf(q), EPSF));
            }
        }
    }
}

// ---------------- K6: fused pairwise mpm ----------------
__global__ void __launch_bounds__(128) k6_pairwise(const float* __restrict__ cp,
                                                   const float* __restrict__ ch,
                                                   const float* __restrict__ params,
                                                   float* __restrict__ outp)
{
    extern __shared__ float sm[];
    float* tile = sm;
    float* w2s  = sm + 12800;
    float* anch = sm + 14800;
    float* invA = sm + 15600;
    float* invT = sm + 15760;
    float* red  = sm + 18448;
    float* part = sm + 23952;

    int tid = threadIdx.x;
    int b = blockIdx.y;
    int dir = blockIdx.z;
    int ib = blockIdx.x;
    int i0 = ib * 8;
    int m = 2 + dir;

    for (int t = tid; t < PP * HH; t += 128) {
        float wv = params[m * PP * HH + t];
        w2s[t] = wv * wv;
    }
    {
        const float* abase = cp + ((size_t)b*LL + i0)*H2 + dir*HH;
        for (int t = tid; t < 8 * 25; t += 128) {
            int a = t / 25, c = t % 25;
            *(float4*)(anch + a*HH + 4*c) = *(const float4*)(abase + (size_t)a*H2 + 4*c);
        }
    }
    {
        const float* tbase = ch + (size_t)b*LL*H2 + dir*HH;
        for (int t = tid; t < 128 * 25; t += 128) {
            int j = t / 25, c = t % 25;
            *(float4*)(tile + j*HH + 4*c) = *(const float4*)(tbase + (size_t)j*H2 + 4*c);
        }
    }
    for (int t = tid; t < 8 * PP; t += 128) {
        int a = t / PP, p = t % PP;
        invA[a*PP + p] = 1.f / fmaxf(g_wnorm[dir][1][b][p][i0 + a], EPSF);
    }
    #pragma unroll
    for (int p = 0; p < PP; p++)
        invT[tid*21 + p] = 1.f / fmaxf(g_wnorm[2 + dir][1][b][p][tid], EPSF);
    __syncthreads();

    float hm[PP], hs[PP];
    #pragma unroll
    for (int p = 0; p < PP; p++) { hm[p] = -INFINITY; hs[p] = 0.f; }

    const ulonglong2* vt = (const ulonglong2*)(tile + tid*HH);
    for (int pass = 0; pass < 4; pass++) {
        int a0 = pass * 2;
        const ulonglong2* at0 = (const ulonglong2*)(anch + a0*HH);
        const ulonglong2* at1 = (const ulonglong2*)(anch + (a0+1)*HH);
        u64 acc0[PP], acc1[PP];
        #pragma unroll
        for (int p = 0; p < PP; p++) { acc0[p] = 0ull; acc1[p] = 0ull; }
        #pragma unroll 5
        for (int c = 0; c < 25; c++) {
            ulonglong2 v  = vt[c];
            ulonglong2 aa = at0[c];
            ulonglong2 bb = at1[c];
            u64 p00 = mul2(v.x, aa.x), p01 = mul2(v.y, aa.y);
            u64 p10 = mul2(v.x, bb.x), p11 = mul2(v.y, bb.y);
            #pragma unroll
            for (int p = 0; p < PP; p++) {
                ulonglong2 w = *((const ulonglong2*)(w2s + p*HH) + c);
                fma2(acc0[p], w.x, p00);
                fma2(acc0[p], w.y, p01);
                fma2(acc1[p], w.x, p10);
                fma2(acc1[p], w.y, p11);
            }
        }
        #pragma unroll
        for (int p = 0; p < PP; p++) {
            float2 x0 = up2(acc0[p]);
            float2 x1 = up2(acc1[p]);
            float it = invT[tid*21 + p];
            float v0 = (x0.x + x0.y) * invA[a0*PP + p] * it;
            float v1 = (x1.x + x1.y) * invA[(a0+1)*PP + p] * it;
            red[tid*43 + p]      = v0;
            red[tid*43 + 21 + p] = v1;
            hm[p] = fmaxf(hm[p], fmaxf(v0, v1));
            hs[p] += v0; hs[p] += v1;
        }
        __syncthreads();
        for (int t = tid; t < 160; t += 128) {
            int a = t / 80, p = (t % 80) >> 2, q = t & 3;
            float mx = -INFINITY, s = 0.f;
            int base = q * 32;
            for (int k = 0; k < 32; k++) {
                float v = red[(base + k)*43 + a*21 + p];
                mx = fmaxf(mx, v); s += v;
            }
            part[t*2] = mx; part[t*2 + 1] = s;
        }
        __syncthreads();
        if (tid < 40) {
            int a = tid / PP, p = tid % PP;
            float mx = -INFINITY, s = 0.f;
            #pragma unroll
            for (int q = 0; q < 4; q++) {
                int t = a*80 + p*4 + q;
                mx = fmaxf(mx, part[t*2]);
                s += part[t*2 + 1];
            }
            float* o = outp + ((size_t)b*LL + i0 + a0 + a)*CC;
            o[46 + dir*40 + p] = mx;
            o[66 + dir*40 + p] = s * (1.f/LL);
        }
    }

    float* gp = &g_hp[dir][b][ib][tid][0];
    #pragma unroll
    for (int p = 0; p < PP; p++) {
        gp[2*p]     = hm[p];
        gp[2*p + 1] = hs[p];
    }
}

// ---------------- K7: reduce mv_h partials ----------------
__global__ void __launch_bounds__(128) k7_reduce(float* __restrict__ out)
{
    int b = blockIdx.x, dir = blockIdx.y, j = threadIdx.x;
    float* o = out + (size_t)BB*LL*CC + ((size_t)b*LL + j)*CC;
    for (int p = 0; p < PP; p++) {
        float mx = -INFINITY, s = 0.f;
        #pragma unroll
        for (int ib = 0; ib < 16; ib++) {
            float2 v = *(const float2*)&g_hp[dir][b][ib][j][2*p];
            mx = fmaxf(mx, v.x); s += v.y;
        }
        o[46 + dir*40 + p] = mx;
        o[66 + dir*40 + p] = s * (1.f/LL);
    }
}

// ---------------- launch ----------------
extern "C" void kernel_launch(void* const* d_in, const int* in_sizes, int n_in,
                              void* d_out, int out_size)
{
    const float* cp     = (const float*)d_in[0];
    const int*   mp     = (const int*)d_in[1];
    const float* ch     = (const float*)d_in[2];
    const int*   mh     = (const int*)d_in[3];
    const float* params = (const float*)d_in[4];
    float* out = (float*)d_out;
    float* out_h = out + (size_t)BB*LL*CC;

    static int attr_done = 0;
    if (!attr_done) {
        cudaFuncSetAttribute(k23_rows,    cudaFuncAttributeMaxDynamicSharedMemorySize, 58960);
        cudaFuncSetAttribute(k4_cols,     cudaFuncAttributeMaxDynamicSharedMemorySize, 55760);
        cudaFuncSetAttribute(k6_pairwise, cudaFuncAttributeMaxDynamicSharedMemorySize, 97088);
        attr_done = 1;
    }

    k1_norms<<<dim3(LL/8, BB), 128>>>(cp, ch, params, mp, mh);
    k23_rows<<<dim3(LL/8, BB, 2), 128, 58960>>>(cp, ch, out);
    k4_cols<<<dim3(LL/8, BB, 2), 128, 55760>>>(cp, out_h);
    k5_vec<<<dim3(LL/4, BB, 2), 128>>>(cp, ch, params, out);
    k6_pairwise<<<dim3(LL/8, BB, 2), 128, 97088>>>(cp, ch, params, out);
    k7_reduce<<<dim3(BB, 2), 128>>>(out);
}

// round 7
// speedup vs baseline: 1.0677x; 1.0677x over previous
#include <cuda_runtime.h>
#include <math.h>

#define BB 16
#define LL 128
#define HH 100
#define H2 200
#define PP 20
#define CC 210
#define EPSF 1e-8f

typedef unsigned long long u64;

__device__ __forceinline__ u64 mul2(u64 a, u64 b) {
    u64 d; asm("mul.rn.f32x2 %0,%1,%2;" : "=l"(d) : "l"(a), "l"(b)); return d;
}
__device__ __forceinline__ void fma2(u64& d, u64 a, u64 b) {
    asm("fma.rn.f32x2 %0,%1,%2,%0;" : "+l"(d) : "l"(a), "l"(b));
}
__device__ __forceinline__ float2 up2(u64 x) {
    float2 r; asm("mov.b64 {%0,%1}, %2;" : "=f"(r.x), "=f"(r.y) : "l"(x)); return r;
}

// ---------------- scratch ----------------
__device__ float g_norm[4][BB][LL];
__device__ float g_wnorm[4][4][BB][PP][LL];
__device__ __align__(16) float g_att[8][BB][LL][HH];
__device__ __align__(16) float g_cos[2][BB][LL][LL];   // [dir][b][i][j]
__device__ int   g_last[2][BB];
__device__ __align__(16) float g_hp[2][BB][16][LL][2*PP];

// ---------------- K1: norms (+ last indices) ----------------
__global__ void __launch_bounds__(128) k1_norms(const float* __restrict__ cp,
                                                const float* __restrict__ ch,
                                                const float* __restrict__ params,
                                                const int* __restrict__ mp,
                                                const int* __restrict__ mh)
{
    int b = blockIdx.y, i0 = blockIdx.x * 8, tid = threadIdx.x;
    __shared__ float vsq[8][4][HH];
    for (int t = tid; t < 8 * 2 * H2; t += 128) {
        int a = t / (2 * H2);
        int rem = t % (2 * H2);
        float v;
        if (rem < H2) v = cp[((size_t)b*LL + i0 + a)*H2 + rem];
        else          v = ch[((size_t)b*LL + i0 + a)*H2 + rem - H2];
        vsq[a][rem / HH][rem % HH] = v * v;
    }
    __syncthreads();
    if (tid < 32) {
        int a = tid >> 2, r = tid & 3;
        float s = 0.f;
        for (int h = 0; h < HH; h++) s += vsq[a][r][h];
        g_norm[r][b][i0 + a] = sqrtf(s);
    }
    for (int t = tid; t < 4 * 4 * PP; t += 128) {
        int r = t / (4 * PP);
        int rem = t % (4 * PP);
        int ml = rem / PP, p = rem % PP;
        int m = (r & 1) ? (2 * ml + 1) : (2 * ml);
        const float* w = params + (m * PP + p) * HH;
        float s[8] = {0,0,0,0,0,0,0,0};
        for (int h = 0; h < HH; h++) {
            float wv = w[h]; float w2 = wv * wv;
            #pragma unroll
            for (int a = 0; a < 8; a++) s[a] += w2 * vsq[a][r][h];
        }
        #pragma unroll
        for (int a = 0; a < 8; a++) g_wnorm[r][ml][b][p][i0 + a] = sqrtf(s[a]);
    }
    if (blockIdx.x == 0 && blockIdx.y == 0 && tid < BB) {
        int lp = 0, lh = 0;
        for (int j = 0; j < LL; j++) { lp += mp[tid*LL + j]; lh += mh[tid*LL + j]; }
        g_last[0][tid] = max(lp - 1, 0);
        g_last[1][tid] = max(lh - 1, 0);
    }
}

// ---------------- K23 (round-4 version): cos + row stats + attentive h ----------------
__global__ void __launch_bounds__(256) k23_rows(const float* __restrict__ cp,
                                                const float* __restrict__ ch,
                                                float* __restrict__ outp)
{
    __shared__ __align__(16) float pan[8 * H2];
    __shared__ float cosr[2 * 8 * LL];
    __shared__ float stat[2 * 8 * 2];

    int b = blockIdx.y, i0 = blockIdx.x * 8, tid = threadIdx.x;

    const float4* psrc = (const float4*)(cp + ((size_t)b*LL + i0)*H2);
    float4* pdst = (float4*)pan;
    for (int t = tid; t < 8 * 50; t += 256) pdst[t] = psrc[t];
    __syncthreads();

    int dir = tid >> 7, j = tid & 127;
    {
        const float4* tr = (const float4*)(ch + ((size_t)b*LL + j)*H2 + dir*HH);
        float nj = g_norm[2 + dir][b][j];
        float dacc[8];
        #pragma unroll
        for (int a = 0; a < 8; a++) dacc[a] = 0.f;
        const float4* pb = (const float4*)(pan + dir*HH);
        #pragma unroll 5
        for (int c = 0; c < 25; c++) {
            float4 v = tr[c];
            #pragma unroll
            for (int a = 0; a < 8; a++) {
                float4 w = pb[a*50 + c];
                dacc[a] += v.x*w.x + v.y*w.y + v.z*w.z + v.w*w.w;
            }
        }
        #pragma unroll
        for (int a = 0; a < 8; a++) {
            float ni = g_norm[dir][b][i0 + a];
            float cv = dacc[a] / fmaxf(ni * nj, EPSF);
            cosr[(dir*8 + a)*128 + j] = cv;
            g_cos[dir][b][i0 + a][j] = cv;
        }
    }
    __syncthreads();

    int w = tid >> 5, lane = tid & 31;
    for (int task = w; task < 16; task += 8) {
        int d = task >> 3, a = task & 7;
        float mx = -INFINITY, s = 0.f;
        for (int jj = lane; jj < 128; jj += 32) {
            float v = cosr[(d*8 + a)*128 + jj];
            mx = fmaxf(mx, v); s += v;
        }
        #pragma unroll
        for (int o = 16; o; o >>= 1) {
            mx = fmaxf(mx, __shfl_xor_sync(0xffffffffu, mx, o));
            s += __shfl_xor_sync(0xffffffffu, s, o);
        }
        if (lane == 0) { stat[(d*8 + a)*2] = mx; stat[(d*8 + a)*2 + 1] = s; }
    }
    __syncthreads();

    if (tid < 8) {
        float* o = outp + ((size_t)b*LL + i0 + tid)*CC;
        o[0] = stat[tid*2];         o[1] = stat[tid*2 + 1] * (1.f/LL);
        o[2] = stat[(8+tid)*2];     o[3] = stat[(8+tid)*2 + 1] * (1.f/LL);
    }

    if (tid < 200) {
        int d = tid >= 100;
        float inv[8], smv[8], mxv[8];
        #pragma unroll
        for (int a = 0; a < 8; a++) {
            inv[a] = 1.f / fmaxf(stat[(d*8 + a)*2 + 1], EPSF);
            smv[a] = 0.f; mxv[a] = -INFINITY;
        }
        const float* crow = cosr + d*8*128;
        const float* gb = ch + (size_t)b*LL*H2 + tid;
        for (int jj = 0; jj < 128; jj += 2) {
            float hv0 = gb[(size_t)jj*H2];
            float hv1 = gb[(size_t)(jj+1)*H2];
            #pragma unroll
            for (int a = 0; a < 8; a++) {
                float2 c2 = *(const float2*)&crow[a*128 + jj];
                float v0 = c2.x * hv0, v1 = c2.y * hv1;
                smv[a] += v0; smv[a] += v1;
                mxv[a] = fmaxf(mxv[a], fmaxf(v0, v1));
            }
        }
        int h = d ? tid - 100 : tid;
        for (int a = 0; a < 8; a++) {
            g_att[d ? 1 : 0][b][i0 + a][h] = smv[a] * inv[a];
            g_att[d ? 5 : 4][b][i0 + a][h] = mxv[a];
        }
    }
}

// ---------------- K4 (round-4 version): col stats + attentive p ----------------
__global__ void __launch_bounds__(256) k4_cols(const float* __restrict__ cp,
                                               float* __restrict__ outh)
{
    __shared__ float cosc[2 * 8 * LL];
    __shared__ float stat[2 * 8 * 2];

    int b = blockIdx.y, j0 = blockIdx.x * 8, tid = threadIdx.x;

    for (int t = tid; t < 2 * 128 * 2; t += 256) {
        int d = t >> 8, rem = t & 255, i = rem >> 1, q = rem & 1;
        float4 v = *(const float4*)&g_cos[d][b][i][j0 + q*4];
        cosc[(d*8 + q*4 + 0)*128 + i] = v.x;
        cosc[(d*8 + q*4 + 1)*128 + i] = v.y;
        cosc[(d*8 + q*4 + 2)*128 + i] = v.z;
        cosc[(d*8 + q*4 + 3)*128 + i] = v.w;
    }
    __syncthreads();

    int w = tid >> 5, lane = tid & 31;
    for (int task = w; task < 16; task += 8) {
        int idx = task * 128;
        float mx = -INFINITY, s = 0.f;
        for (int ii = lane; ii < 128; ii += 32) {
            float v = cosc[idx + ii];
            mx = fmaxf(mx, v); s += v;
        }
        #pragma unroll
        for (int o = 16; o; o >>= 1) {
            mx = fmaxf(mx, __shfl_xor_sync(0xffffffffu, mx, o));
            s += __shfl_xor_sync(0xffffffffu, s, o);
        }
        if (lane == 0) { stat[task*2] = mx; stat[task*2 + 1] = s; }
    }
    __syncthreads();

    if (tid < 8) {
        float* o = outh + ((size_t)b*LL + j0 + tid)*CC;
        o[0] = stat[tid*2];         o[1] = stat[tid*2 + 1] * (1.f/LL);
        o[2] = stat[(8+tid)*2];     o[3] = stat[(8+tid)*2 + 1] * (1.f/LL);
    }

    if (tid < 200) {
        int d = tid >= 100;
        float inv[8], smv[8], mxv[8];
        #pragma unroll
        for (int a = 0; a < 8; a++) {
            inv[a] = 1.f / fmaxf(stat[(d*8 + a)*2 + 1], EPSF);
            smv[a] = 0.f; mxv[a] = -INFINITY;
        }
        const float* crow = cosc + d*8*128;
        const float* gb = cp + (size_t)b*LL*H2 + tid;
        for (int ii = 0; ii < 128; ii += 2) {
            float pv0 = gb[(size_t)ii*H2];
            float pv1 = gb[(size_t)(ii+1)*H2];
            #pragma unroll
            for (int a = 0; a < 8; a++) {
                float2 c2 = *(const float2*)&crow[a*128 + ii];
                float v0 = c2.x * pv0, v1 = c2.y * pv1;
                smv[a] += v0; smv[a] += v1;
                mxv[a] = fmaxf(mxv[a], fmaxf(v0, v1));
            }
        }
        int h = d ? tid - 100 : tid;
        for (int a = 0; a < 8; a++) {
            g_att[d ? 3 : 2][b][j0 + a][h] = smv[a] * inv[a];
            g_att[d ? 7 : 6][b][j0 + a][h] = mxv[a];
        }
    }
}

// ---------------- K5: vector-mpm groups (loop-interchanged, single pass) ----------------
__global__ void __launch_bounds__(128) k5_vec(const float* __restrict__ cp,
                                              const float* __restrict__ ch,
                                              const float* __restrict__ params,
                                              float* __restrict__ out)
{
    int b = blockIdx.y, side = blockIdx.z, i0 = blockIdx.x * 4, tid = threadIdx.x;
    __shared__ __align__(16) float v1s[4][2][HH];
    __shared__ __align__(16) float v2f[2][HH];
    __shared__ __align__(16) float v2a[4][4][HH];
    const float* base1 = side == 0 ? cp : ch;
    const float* other = side == 0 ? ch : cp;
    for (int t = tid; t < 4 * H2; t += 128) {
        int a = t / H2, rem = t % H2;
        v1s[a][rem / HH][rem % HH] = base1[((size_t)b*LL + i0 + a)*H2 + rem];
    }
    int lastIdx = g_last[side == 0 ? 1 : 0][b];
    for (int t = tid; t < H2; t += 128) {
        if (t < HH) v2f[0][t] = other[((size_t)b*LL + lastIdx)*H2 + t];
        else        v2f[1][t - HH] = other[(size_t)b*LL*H2 + t];
    }
    int a0 = side == 0 ? 0 : 2, a4 = side == 0 ? 4 : 6;
    for (int t = tid; t < 4 * 4 * HH; t += 128) {
        int a = t / (4 * HH);
        int g = (t / HH) % 4;
        int h = t % HH;
        int att = (g < 2) ? (a0 + g) : (a4 + g - 2);
        v2a[a][g][h] = g_att[att][b][i0 + a][h];
    }
    __syncthreads();
    if (tid < 120) {
        int g = tid / PP, p = tid % PP;
        const int mtab[6] = {0, 1, 4, 5, 6, 7};
        const int btab[6] = {4, 25, 126, 147, 168, 189};
        int m = mtab[g], dir = g & 1, base = btab[g];
        int rowset = side * 2 + dir;
        const float4* w4 = (const float4*)(params + (m * PP + p) * HH);
        bool p0 = (p == 0);

        const float4* v14[4];
        const float4* v24[4];
        #pragma unroll
        for (int a = 0; a < 4; a++) {
            v14[a] = (const float4*)v1s[a][dir];
            v24[a] = (g == 0) ? (const float4*)v2f[0]
                   : (g == 1) ? (const float4*)v2f[1]
                              : (const float4*)v2a[a][g - 2];
        }

        float s12[4] = {0,0,0,0}, s22[4] = {0,0,0,0};
        float dd[4]  = {0,0,0,0}, qq[4]  = {0,0,0,0};

        #pragma unroll 5
        for (int c = 0; c < 25; c++) {
            float4 w = w4[c];
            float w2x = w.x*w.x, w2y = w.y*w.y, w2z = w.z*w.z, w2w = w.w*w.w;
            #pragma unroll
            for (int a = 0; a < 4; a++) {
                float4 x = v24[a][c], v1 = v14[a][c];
                s12[a] += w2x*v1.x*x.x + w2y*v1.y*x.y + w2z*v1.z*x.z + w2w*v1.w*x.w;
                s22[a] += w2x*x.x*x.x  + w2y*x.y*x.y  + w2z*x.z*x.z  + w2w*x.w*x.w;
                if (p0) {
                    dd[a] += v1.x*x.x + v1.y*x.y + v1.z*x.z + v1.w*x.w;
                    qq[a] += x.x*x.x + x.y*x.y + x.z*x.z + x.w*x.w;
                }
            }
        }

        #pragma unroll
        for (int a = 0; a < 4; a++) {
            float n1 = g_wnorm[rowset][m >> 1][b][p][i0 + a];
            float val = s12[a] / (fmaxf(n1, EPSF) * fmaxf(sqrtf(s22[a]), EPSF));
            float* o = out + ((size_t)side*BB*LL + (size_t)b*LL + i0 + a)*CC;
            o[base + 1 + p] = val;
            if (p0) {
                float pn = g_norm[rowset][b][i0 + a];
                o[base] = dd[a] / (fmaxf(pn, EPSF) * fmaxf(sqrtf(qq[a]), EPSF));
            }
        }
    }
}

// ---------------- K6: fused pairwise mpm ----------------
__global__ void __launch_bounds__(128) k6_pairwise(const float* __restrict__ cp,
                                                   const float* __restrict__ ch,
                                                   const float* __restrict__ params,
                                                   float* __restrict__ outp)
{
    extern __shared__ float sm[];
    float* tile = sm;
    float* w2s  = sm + 12800;
    float* anch = sm + 14800;
    float* invA = sm + 15600;
    float* invT = sm + 15760;
    float* red  = sm + 18448;
    float* part = sm + 23952;

    int tid = threadIdx.x;
    int b = blockIdx.y;
    int dir = blockIdx.z;
    int ib = blockIdx.x;
    int i0 = ib * 8;
    int m = 2 + dir;

    for (int t = tid; t < PP * HH; t += 128) {
        float wv = params[m * PP * HH + t];
        w2s[t] = wv * wv;
    }
    {
        const float* abase = cp + ((size_t)b*LL + i0)*H2 + dir*HH;
        for (int t = tid; t < 8 * 25; t += 128) {
            int a = t / 25, c = t % 25;
            *(float4*)(anch + a*HH + 4*c) = *(const float4*)(abase + (size_t)a*H2 + 4*c);
        }
    }
    {
        const float* tbase = ch + (size_t)b*LL*H2 + dir*HH;
        for (int t = tid; t < 128 * 25; t += 128) {
            int j = t / 25, c = t % 25;
            *(float4*)(tile + j*HH + 4*c) = *(const float4*)(tbase + (size_t)j*H2 + 4*c);
        }
    }
    for (int t = tid; t < 8 * PP; t += 128) {
        int a = t / PP, p = t % PP;
        invA[a*PP + p] = 1.f / fmaxf(g_wnorm[dir][1][b][p][i0 + a], EPSF);
    }
    #pragma unroll
    for (int p = 0; p < PP; p++)
        invT[tid*21 + p] = 1.f / fmaxf(g_wnorm[2 + dir][1][b][p][tid], EPSF);
    __syncthreads();

    float hm[PP], hs[PP];
    #pragma unroll
    for (int p = 0; p < PP; p++) { hm[p] = -INFINITY; hs[p] = 0.f; }

    const ulonglong2* vt = (const ulonglong2*)(tile + tid*HH);
    for (int pass = 0; pass < 4; pass++) {
        int a0 = pass * 2;
        const ulonglong2* at0 = (const ulonglong2*)(anch + a0*HH);
        const ulonglong2* at1 = (const ulonglong2*)(anch + (a0+1)*HH);
        u64 acc0[PP], acc1[PP];
        #pragma unroll
        for (int p = 0; p < PP; p++) { acc0[p] = 0ull; acc1[p] = 0ull; }
        #pragma unroll 5
        for (int c = 0; c < 25; c++) {
            ulonglong2 v  = vt[c];
            ulonglong2 aa = at0[c];
            ulonglong2 bb = at1[c];
            u64 p00 = mul2(v.x, aa.x), p01 = mul2(v.y, aa.y);
            u64 p10 = mul2(v.x, bb.x), p11 = mul2(v.y, bb.y);
            #pragma unroll
            for (int p = 0; p < PP; p++) {
                ulonglong2 w = *((const ulonglong2*)(w2s + p*HH) + c);
                fma2(acc0[p], w.x, p00);
                fma2(acc0[p], w.y, p01);
                fma2(acc1[p], w.x, p10);
                fma2(acc1[p], w.y, p11);
            }
        }
        #pragma unroll
        for (int p = 0; p < PP; p++) {
            float2 x0 = up2(acc0[p]);
            float2 x1 = up2(acc1[p]);
            float it = invT[tid*21 + p];
            float v0 = (x0.x + x0.y) * invA[a0*PP + p] * it;
            float v1 = (x1.x + x1.y) * invA[(a0+1)*PP + p] * it;
            red[tid*43 + p]      = v0;
            red[tid*43 + 21 + p] = v1;
            hm[p] = fmaxf(hm[p], fmaxf(v0, v1));
            hs[p] += v0; hs[p] += v1;
        }
        __syncthreads();
        for (int t = tid; t < 160; t += 128) {
            int a = t / 80, p = (t % 80) >> 2, q = t & 3;
            float mx = -INFINITY, s = 0.f;
            int base = q * 32;
            for (int k = 0; k < 32; k++) {
                float v = red[(base + k)*43 + a*21 + p];
                mx = fmaxf(mx, v); s += v;
            }
            part[t*2] = mx; part[t*2 + 1] = s;
        }
        __syncthreads();
        if (tid < 40) {
            int a = tid / PP, p = tid % PP;
            float mx = -INFINITY, s = 0.f;
            #pragma unroll
            for (int q = 0; q < 4; q++) {
                int t = a*80 + p*4 + q;
                mx = fmaxf(mx, part[t*2]);
                s += part[t*2 + 1];
            }
            float* o = outp + ((size_t)b*LL + i0 + a0 + a)*CC;
            o[46 + dir*40 + p] = mx;
            o[66 + dir*40 + p] = s * (1.f/LL);
        }
    }

    float* gp = &g_hp[dir][b][ib][tid][0];
    #pragma unroll
    for (int p = 0; p < PP; p++) {
        gp[2*p]     = hm[p];
        gp[2*p + 1] = hs[p];
    }
}

// ---------------- K7: reduce mv_h partials ----------------
__global__ void __launch_bounds__(128) k7_reduce(float* __restrict__ out)
{
    int b = blockIdx.x, dir = blockIdx.y, j = threadIdx.x;
    float* o = out + (size_t)BB*LL*CC + ((size_t)b*LL + j)*CC;
    for (int p = 0; p < PP; p++) {
        float mx = -INFINITY, s = 0.f;
        #pragma unroll
        for (int ib = 0; ib < 16; ib++) {
            float2 v = *(const float2*)&g_hp[dir][b][ib][j][2*p];
            mx = fmaxf(mx, v.x); s += v.y;
        }
        o[46 + dir*40 + p] = mx;
        o[66 + dir*40 + p] = s * (1.f/LL);
    }
}

// ---------------- launch ----------------
extern "C" void kernel_launch(void* const* d_in, const int* in_sizes, int n_in,
                              void* d_out, int out_size)
{
    const float* cp     = (const float*)d_in[0];
    const int*   mp     = (const int*)d_in[1];
    const float* ch     = (const float*)d_in[2];
    const int*   mh     = (const int*)d_in[3];
    const float* params = (const float*)d_in[4];
    float* out = (float*)d_out;
    float* out_h = out + (size_t)BB*LL*CC;

    static int attr_done = 0;
    if (!attr_done) {
        cudaFuncSetAttribute(k6_pairwise, cudaFuncAttributeMaxDynamicSharedMemorySize, 97088);
        attr_done = 1;
    }

    k1_norms<<<dim3(LL/8, BB), 128>>>(cp, ch, params, mp, mh);
    k23_rows<<<dim3(LL/8, BB), 256>>>(cp, ch, out);
    k4_cols<<<dim3(LL/8, BB), 256>>>(cp, out_h);
    k5_vec<<<dim3(LL/4, BB, 2), 128>>>(cp, ch, params, out);
    k6_pairwise<<<dim3(LL/8, BB, 2), 128, 97088>>>(cp, ch, params, out);
    k7_reduce<<<dim3(BB, 2), 128>>>(out);
}

// round 8
// speedup vs baseline: 1.1756x; 1.1011x over previous
#include <cuda_runtime.h>
#include <math.h>

#define BB 16
#define LL 128
#define HH 100
#define H2 200
#define PP 20
#define CC 210
#define EPSF 1e-8f

typedef unsigned long long u64;

__device__ __forceinline__ u64 mul2(u64 a, u64 b) {
    u64 d; asm("mul.rn.f32x2 %0,%1,%2;" : "=l"(d) : "l"(a), "l"(b)); return d;
}
__device__ __forceinline__ void fma2(u64& d, u64 a, u64 b) {
    asm("fma.rn.f32x2 %0,%1,%2,%0;" : "+l"(d) : "l"(a), "l"(b));
}
__device__ __forceinline__ float2 up2(u64 x) {
    float2 r; asm("mov.b64 {%0,%1}, %2;" : "=f"(r.x), "=f"(r.y) : "l"(x)); return r;
}

// ---------------- scratch ----------------
__device__ float g_norm[4][BB][LL];
__device__ float g_wnorm[4][4][BB][PP][LL];
__device__ __align__(16) float g_att[8][BB][LL][HH];
__device__ __align__(16) float g_cos[2][BB][LL][LL];   // [dir][b][i][j]
__device__ int   g_last[2][BB];
__device__ __align__(16) float g_hp[2][BB][16][LL][2*PP];

// ---------------- K1: norms (+ last indices) ----------------
__global__ void __launch_bounds__(128) k1_norms(const float* __restrict__ cp,
                                                const float* __restrict__ ch,
                                                const float* __restrict__ params,
                                                const int* __restrict__ mp,
                                                const int* __restrict__ mh)
{
    int b = blockIdx.y, i0 = blockIdx.x * 8, tid = threadIdx.x;
    __shared__ float vsq[8][4][HH];
    for (int t = tid; t < 8 * 2 * H2; t += 128) {
        int a = t / (2 * H2);
        int rem = t % (2 * H2);
        float v;
        if (rem < H2) v = cp[((size_t)b*LL + i0 + a)*H2 + rem];
        else          v = ch[((size_t)b*LL + i0 + a)*H2 + rem - H2];
        vsq[a][rem / HH][rem % HH] = v * v;
    }
    __syncthreads();
    if (tid < 32) {
        int a = tid >> 2, r = tid & 3;
        float s = 0.f;
        for (int h = 0; h < HH; h++) s += vsq[a][r][h];
        g_norm[r][b][i0 + a] = sqrtf(s);
    }
    for (int t = tid; t < 4 * 4 * PP; t += 128) {
        int r = t / (4 * PP);
        int rem = t % (4 * PP);
        int ml = rem / PP, p = rem % PP;
        int m = (r & 1) ? (2 * ml + 1) : (2 * ml);
        const float* w = params + (m * PP + p) * HH;
        float s[8] = {0,0,0,0,0,0,0,0};
        for (int h = 0; h < HH; h++) {
            float wv = w[h]; float w2 = wv * wv;
            #pragma unroll
            for (int a = 0; a < 8; a++) s[a] += w2 * vsq[a][r][h];
        }
        #pragma unroll
        for (int a = 0; a < 8; a++) g_wnorm[r][ml][b][p][i0 + a] = sqrtf(s[a]);
    }
    if (blockIdx.x == 0 && blockIdx.y == 0 && tid < BB) {
        int lp = 0, lh = 0;
        for (int j = 0; j < LL; j++) { lp += mp[tid*LL + j]; lh += mh[tid*LL + j]; }
        g_last[0][tid] = max(lp - 1, 0);
        g_last[1][tid] = max(lh - 1, 0);
    }
}

// ---------------- K23: cos + row stats + attentive h ----------------
__global__ void __launch_bounds__(256) k23_rows(const float* __restrict__ cp,
                                                const float* __restrict__ ch,
                                                float* __restrict__ outp)
{
    __shared__ __align__(16) float pan[8 * H2];
    __shared__ float cosr[2 * 8 * LL];
    __shared__ float stat[2 * 8 * 2];

    int b = blockIdx.y, i0 = blockIdx.x * 8, tid = threadIdx.x;

    const float4* psrc = (const float4*)(cp + ((size_t)b*LL + i0)*H2);
    float4* pdst = (float4*)pan;
    for (int t = tid; t < 8 * 50; t += 256) pdst[t] = psrc[t];
    __syncthreads();

    int dir = tid >> 7, j = tid & 127;
    {
        const float4* tr = (const float4*)(ch + ((size_t)b*LL + j)*H2 + dir*HH);
        float nj = g_norm[2 + dir][b][j];
        float dacc[8];
        #pragma unroll
        for (int a = 0; a < 8; a++) dacc[a] = 0.f;
        const float4* pb = (const float4*)(pan + dir*HH);
        #pragma unroll 5
        for (int c = 0; c < 25; c++) {
            float4 v = tr[c];
            #pragma unroll
            for (int a = 0; a < 8; a++) {
                float4 w = pb[a*50 + c];
                dacc[a] += v.x*w.x + v.y*w.y + v.z*w.z + v.w*w.w;
            }
        }
        #pragma unroll
        for (int a = 0; a < 8; a++) {
            float ni = g_norm[dir][b][i0 + a];
            float cv = dacc[a] / fmaxf(ni * nj, EPSF);
            cosr[(dir*8 + a)*128 + j] = cv;
            g_cos[dir][b][i0 + a][j] = cv;
        }
    }
    __syncthreads();

    int w = tid >> 5, lane = tid & 31;
    for (int task = w; task < 16; task += 8) {
        int d = task >> 3, a = task & 7;
        float mx = -INFINITY, s = 0.f;
        for (int jj = lane; jj < 128; jj += 32) {
            float v = cosr[(d*8 + a)*128 + jj];
            mx = fmaxf(mx, v); s += v;
        }
        #pragma unroll
        for (int o = 16; o; o >>= 1) {
            mx = fmaxf(mx, __shfl_xor_sync(0xffffffffu, mx, o));
            s += __shfl_xor_sync(0xffffffffu, s, o);
        }
        if (lane == 0) { stat[(d*8 + a)*2] = mx; stat[(d*8 + a)*2 + 1] = s; }
    }
    __syncthreads();

    if (tid < 8) {
        float* o = outp + ((size_t)b*LL + i0 + tid)*CC;
        o[0] = stat[tid*2];         o[1] = stat[tid*2 + 1] * (1.f/LL);
        o[2] = stat[(8+tid)*2];     o[3] = stat[(8+tid)*2 + 1] * (1.f/LL);
    }

    if (tid < 200) {
        int d = tid >= 100;
        float inv[8], smv[8], mxv[8];
        #pragma unroll
        for (int a = 0; a < 8; a++) {
            inv[a] = 1.f / fmaxf(stat[(d*8 + a)*2 + 1], EPSF);
            smv[a] = 0.f; mxv[a] = -INFINITY;
        }
        const float* crow = cosr + d*8*128;
        const float* gb = ch + (size_t)b*LL*H2 + tid;
        for (int jj = 0; jj < 128; jj += 2) {
            float hv0 = gb[(size_t)jj*H2];
            float hv1 = gb[(size_t)(jj+1)*H2];
            #pragma unroll
            for (int a = 0; a < 8; a++) {
                float2 c2 = *(const float2*)&crow[a*128 + jj];
                float v0 = c2.x * hv0, v1 = c2.y * hv1;
                smv[a] += v0; smv[a] += v1;
                mxv[a] = fmaxf(mxv[a], fmaxf(v0, v1));
            }
        }
        int h = d ? tid - 100 : tid;
        for (int a = 0; a < 8; a++) {
            g_att[d ? 1 : 0][b][i0 + a][h] = smv[a] * inv[a];
            g_att[d ? 5 : 4][b][i0 + a][h] = mxv[a];
        }
    }
}

// ---------------- K4: col stats + attentive p ----------------
__global__ void __launch_bounds__(256) k4_cols(const float* __restrict__ cp,
                                               float* __restrict__ outh)
{
    __shared__ float cosc[2 * 8 * LL];
    __shared__ float stat[2 * 8 * 2];

    int b = blockIdx.y, j0 = blockIdx.x * 8, tid = threadIdx.x;

    for (int t = tid; t < 2 * 128 * 2; t += 256) {
        int d = t >> 8, rem = t & 255, i = rem >> 1, q = rem & 1;
        float4 v = *(const float4*)&g_cos[d][b][i][j0 + q*4];
        cosc[(d*8 + q*4 + 0)*128 + i] = v.x;
        cosc[(d*8 + q*4 + 1)*128 + i] = v.y;
        cosc[(d*8 + q*4 + 2)*128 + i] = v.z;
        cosc[(d*8 + q*4 + 3)*128 + i] = v.w;
    }
    __syncthreads();

    int w = tid >> 5, lane = tid & 31;
    for (int task = w; task < 16; task += 8) {
        int idx = task * 128;
        float mx = -INFINITY, s = 0.f;
        for (int ii = lane; ii < 128; ii += 32) {
            float v = cosc[idx + ii];
            mx = fmaxf(mx, v); s += v;
        }
        #pragma unroll
        for (int o = 16; o; o >>= 1) {
            mx = fmaxf(mx, __shfl_xor_sync(0xffffffffu, mx, o));
            s += __shfl_xor_sync(0xffffffffu, s, o);
        }
        if (lane == 0) { stat[task*2] = mx; stat[task*2 + 1] = s; }
    }
    __syncthreads();

    if (tid < 8) {
        float* o = outh + ((size_t)b*LL + j0 + tid)*CC;
        o[0] = stat[tid*2];         o[1] = stat[tid*2 + 1] * (1.f/LL);
        o[2] = stat[(8+tid)*2];     o[3] = stat[(8+tid)*2 + 1] * (1.f/LL);
    }

    if (tid < 200) {
        int d = tid >= 100;
        float inv[8], smv[8], mxv[8];
        #pragma unroll
        for (int a = 0; a < 8; a++) {
            inv[a] = 1.f / fmaxf(stat[(d*8 + a)*2 + 1], EPSF);
            smv[a] = 0.f; mxv[a] = -INFINITY;
        }
        const float* crow = cosc + d*8*128;
        const float* gb = cp + (size_t)b*LL*H2 + tid;
        for (int ii = 0; ii < 128; ii += 2) {
            float pv0 = gb[(size_t)ii*H2];
            float pv1 = gb[(size_t)(ii+1)*H2];
            #pragma unroll
            for (int a = 0; a < 8; a++) {
                float2 c2 = *(const float2*)&crow[a*128 + ii];
                float v0 = c2.x * pv0, v1 = c2.y * pv1;
                smv[a] += v0; smv[a] += v1;
                mxv[a] = fmaxf(mxv[a], fmaxf(v0, v1));
            }
        }
        int h = d ? tid - 100 : tid;
        for (int a = 0; a < 8; a++) {
            g_att[d ? 3 : 2][b][j0 + a][h] = smv[a] * inv[a];
            g_att[d ? 7 : 6][b][j0 + a][h] = mxv[a];
        }
    }
}

// ---------------- K5: vector-mpm groups ----------------
__global__ void __launch_bounds__(128) k5_vec(const float* __restrict__ cp,
                                              const float* __restrict__ ch,
                                              const float* __restrict__ params,
                                              float* __restrict__ out)
{
    int b = blockIdx.y, side = blockIdx.z, i0 = blockIdx.x * 4, tid = threadIdx.x;
    __shared__ __align__(16) float v1s[4][2][HH];
    __shared__ __align__(16) float v2f[2][HH];
    __shared__ __align__(16) float v2a[4][4][HH];
    const float* base1 = side == 0 ? cp : ch;
    const float* other = side == 0 ? ch : cp;
    for (int t = tid; t < 4 * H2; t += 128) {
        int a = t / H2, rem = t % H2;
        v1s[a][rem / HH][rem % HH] = base1[((size_t)b*LL + i0 + a)*H2 + rem];
    }
    int lastIdx = g_last[side == 0 ? 1 : 0][b];
    for (int t = tid; t < H2; t += 128) {
        if (t < HH) v2f[0][t] = other[((size_t)b*LL + lastIdx)*H2 + t];
        else        v2f[1][t - HH] = other[(size_t)b*LL*H2 + t];
    }
    int a0 = side == 0 ? 0 : 2, a4 = side == 0 ? 4 : 6;
    for (int t = tid; t < 4 * 4 * HH; t += 128) {
        int a = t / (4 * HH);
        int g = (t / HH) % 4;
        int h = t % HH;
        int att = (g < 2) ? (a0 + g) : (a4 + g - 2);
        v2a[a][g][h] = g_att[att][b][i0 + a][h];
    }
    __syncthreads();
    if (tid < 120) {
        int g = tid / PP, p = tid % PP;
        const int mtab[6] = {0, 1, 4, 5, 6, 7};
        const int btab[6] = {4, 25, 126, 147, 168, 189};
        int m = mtab[g], dir = g & 1, base = btab[g];
        int rowset = side * 2 + dir;
        const float4* w4 = (const float4*)(params + (m * PP + p) * HH);
        bool p0 = (p == 0);

        const float4* v14[4];
        const float4* v24[4];
        #pragma unroll
        for (int a = 0; a < 4; a++) {
            v14[a] = (const float4*)v1s[a][dir];
            v24[a] = (g == 0) ? (const float4*)v2f[0]
                   : (g == 1) ? (const float4*)v2f[1]
                              : (const float4*)v2a[a][g - 2];
        }

        float s12[4] = {0,0,0,0}, s22[4] = {0,0,0,0};
        float dd[4]  = {0,0,0,0}, qq[4]  = {0,0,0,0};

        #pragma unroll 5
        for (int c = 0; c < 25; c++) {
            float4 w = w4[c];
            float w2x = w.x*w.x, w2y = w.y*w.y, w2z = w.z*w.z, w2w = w.w*w.w;
            #pragma unroll
            for (int a = 0; a < 4; a++) {
                float4 x = v24[a][c], v1 = v14[a][c];
                s12[a] += w2x*v1.x*x.x + w2y*v1.y*x.y + w2z*v1.z*x.z + w2w*v1.w*x.w;
                s22[a] += w2x*x.x*x.x  + w2y*x.y*x.y  + w2z*x.z*x.z  + w2w*x.w*x.w;
                if (p0) {
                    dd[a] += v1.x*x.x + v1.y*x.y + v1.z*x.z + v1.w*x.w;
                    qq[a] += x.x*x.x + x.y*x.y + x.z*x.z + x.w*x.w;
                }
            }
        }

        #pragma unroll
        for (int a = 0; a < 4; a++) {
            float n1 = g_wnorm[rowset][m >> 1][b][p][i0 + a];
            float val = s12[a] / (fmaxf(n1, EPSF) * fmaxf(sqrtf(s22[a]), EPSF));
            float* o = out + ((size_t)side*BB*LL + (size_t)b*LL + i0 + a)*CC;
            o[base + 1 + p] = val;
            if (p0) {
                float pn = g_norm[rowset][b][i0 + a];
                o[base] = dd[a] / (fmaxf(pn, EPSF) * fmaxf(sqrtf(qq[a]), EPSF));
            }
        }
    }
}

// ---------------- K6: fused pairwise mpm ----------------
__global__ void __launch_bounds__(128) k6_pairwise(const float* __restrict__ cp,
                                                   const float* __restrict__ ch,
                                                   const float* __restrict__ params,
                                                   float* __restrict__ outp)
{
    extern __shared__ float sm[];
    float* tile = sm;
    float* w2s  = sm + 12800;
    float* anch = sm + 14800;
    float* invA = sm + 15600;
    float* invT = sm + 15760;
    float* red  = sm + 18448;
    float* part = sm + 23952;

    int tid = threadIdx.x;
    int b = blockIdx.y;
    int dir = blockIdx.z;
    int ib = blockIdx.x;
    int i0 = ib * 8;
    int m = 2 + dir;

    for (int t = tid; t < PP * HH; t += 128) {
        float wv = params[m * PP * HH + t];
        w2s[t] = wv * wv;
    }
    {
        const float* abase = cp + ((size_t)b*LL + i0)*H2 + dir*HH;
        for (int t = tid; t < 8 * 25; t += 128) {
            int a = t / 25, c = t % 25;
            *(float4*)(anch + a*HH + 4*c) = *(const float4*)(abase + (size_t)a*H2 + 4*c);
        }
    }
    {
        const float* tbase = ch + (size_t)b*LL*H2 + dir*HH;
        for (int t = tid; t < 128 * 25; t += 128) {
            int j = t / 25, c = t % 25;
            *(float4*)(tile + j*HH + 4*c) = *(const float4*)(tbase + (size_t)j*H2 + 4*c);
        }
    }
    for (int t = tid; t < 8 * PP; t += 128) {
        int a = t / PP, p = t % PP;
        invA[a*PP + p] = 1.f / fmaxf(g_wnorm[dir][1][b][p][i0 + a], EPSF);
    }
    #pragma unroll
    for (int p = 0; p < PP; p++)
        invT[tid*21 + p] = 1.f / fmaxf(g_wnorm[2 + dir][1][b][p][tid], EPSF);
    __syncthreads();

    float hm[PP], hs[PP];
    #pragma unroll
    for (int p = 0; p < PP; p++) { hm[p] = -INFINITY; hs[p] = 0.f; }

    const ulonglong2* vt = (const ulonglong2*)(tile + tid*HH);
    for (int pass = 0; pass < 4; pass++) {
        int a0 = pass * 2;
        const ulonglong2* at0 = (const ulonglong2*)(anch + a0*HH);
        const ulonglong2* at1 = (const ulonglong2*)(anch + (a0+1)*HH);
        u64 acc0[PP], acc1[PP];
        #pragma unroll
        for (int p = 0; p < PP; p++) { acc0[p] = 0ull; acc1[p] = 0ull; }
        #pragma unroll 5
        for (int c = 0; c < 25; c++) {
            ulonglong2 v  = vt[c];
            ulonglong2 aa = at0[c];
            ulonglong2 bb = at1[c];
            u64 p00 = mul2(v.x, aa.x), p01 = mul2(v.y, aa.y);
            u64 p10 = mul2(v.x, bb.x), p11 = mul2(v.y, bb.y);
            #pragma unroll
            for (int p = 0; p < PP; p++) {
                ulonglong2 w = *((const ulonglong2*)(w2s + p*HH) + c);
                fma2(acc0[p], w.x, p00);
                fma2(acc0[p], w.y, p01);
                fma2(acc1[p], w.x, p10);
                fma2(acc1[p], w.y, p11);
            }
        }
        #pragma unroll
        for (int p = 0; p < PP; p++) {
            float2 x0 = up2(acc0[p]);
            float2 x1 = up2(acc1[p]);
            float it = invT[tid*21 + p];
            float v0 = (x0.x + x0.y) * invA[a0*PP + p] * it;
            float v1 = (x1.x + x1.y) * invA[(a0+1)*PP + p] * it;
            red[tid*43 + p]      = v0;
            red[tid*43 + 21 + p] = v1;
            hm[p] = fmaxf(hm[p], fmaxf(v0, v1));
            hs[p] += v0; hs[p] += v1;
        }
        __syncthreads();
        for (int t = tid; t < 160; t += 128) {
            int a = t / 80, p = (t % 80) >> 2, q = t & 3;
            float mx = -INFINITY, s = 0.f;
            int base = q * 32;
            for (int k = 0; k < 32; k++) {
                float v = red[(base + k)*43 + a*21 + p];
                mx = fmaxf(mx, v); s += v;
            }
            part[t*2] = mx; part[t*2 + 1] = s;
        }
        __syncthreads();
        if (tid < 40) {
            int a = tid / PP, p = tid % PP;
            float mx = -INFINITY, s = 0.f;
            #pragma unroll
            for (int q = 0; q < 4; q++) {
                int t = a*80 + p*4 + q;
                mx = fmaxf(mx, part[t*2]);
                s += part[t*2 + 1];
            }
            float* o = outp + ((size_t)b*LL + i0 + a0 + a)*CC;
            o[46 + dir*40 + p] = mx;
            o[66 + dir*40 + p] = s * (1.f/LL);
        }
    }

    float* gp = &g_hp[dir][b][ib][tid][0];
    #pragma unroll
    for (int p = 0; p < PP; p++) {
        gp[2*p]     = hm[p];
        gp[2*p + 1] = hs[p];
    }
}

// ---------------- K7: reduce mv_h partials ----------------
__global__ void __launch_bounds__(128) k7_reduce(float* __restrict__ out)
{
    int b = blockIdx.x, dir = blockIdx.y, j = threadIdx.x;
    float* o = out + (size_t)BB*LL*CC + ((size_t)b*LL + j)*CC;
    for (int p = 0; p < PP; p++) {
        float mx = -INFINITY, s = 0.f;
        #pragma unroll
        for (int ib = 0; ib < 16; ib++) {
            float2 v = *(const float2*)&g_hp[dir][b][ib][j][2*p];
            mx = fmaxf(mx, v.x); s += v.y;
        }
        o[46 + dir*40 + p] = mx;
        o[66 + dir*40 + p] = s * (1.f/LL);
    }
}

// ---------------- launch ----------------
extern "C" void kernel_launch(void* const* d_in, const int* in_sizes, int n_in,
                              void* d_out, int out_size)
{
    const float* cp     = (const float*)d_in[0];
    const int*   mp     = (const int*)d_in[1];
    const float* ch     = (const float*)d_in[2];
    const int*   mh     = (const int*)d_in[3];
    const float* params = (const float*)d_in[4];
    float* out = (float*)d_out;
    float* out_h = out + (size_t)BB*LL*CC;

    static cudaStream_t s1 = 0;
    static cudaEvent_t evFork = 0, evJoin = 0;
    static int init_done = 0;
    if (!init_done) {
        cudaFuncSetAttribute(k6_pairwise, cudaFuncAttributeMaxDynamicSharedMemorySize, 97088);
        cudaStreamCreateWithFlags(&s1, cudaStreamNonBlocking);
        cudaEventCreateWithFlags(&evFork, cudaEventDisableTiming);
        cudaEventCreateWithFlags(&evJoin, cudaEventDisableTiming);
        init_done = 1;
    }

    // main stream: k1 -> fork
    k1_norms<<<dim3(LL/8, BB), 128>>>(cp, ch, params, mp, mh);
    cudaEventRecord(evFork, 0);
    cudaStreamWaitEvent(s1, evFork, 0);

    // side branch: k6 -> k7 (depends only on k1; writes out channels 46..125)
    k6_pairwise<<<dim3(LL/8, BB, 2), 128, 97088, s1>>>(cp, ch, params, out);
    k7_reduce<<<dim3(BB, 2), 128, 0, s1>>>(out);

    // main branch: k23 -> k4 -> k5
    k23_rows<<<dim3(LL/8, BB), 256>>>(cp, ch, out);
    k4_cols<<<dim3(LL/8, BB), 256>>>(cp, out_h);
    k5_vec<<<dim3(LL/4, BB, 2), 128>>>(cp, ch, params, out);

    // join
    cudaEventRecord(evJoin, s1);
    cudaStreamWaitEvent(0, evJoin, 0);
}

// round 9
// speedup vs baseline: 1.1823x; 1.0057x over previous
#include <cuda_runtime.h>
#include <math.h>

#define BB 16
#define LL 128
#define HH 100
#define H2 200
#define PP 20
#define CC 210
#define EPSF 1e-8f

typedef unsigned long long u64;

__device__ __forceinline__ u64 mul2(u64 a, u64 b) {
    u64 d; asm("mul.rn.f32x2 %0,%1,%2;" : "=l"(d) : "l"(a), "l"(b)); return d;
}
__device__ __forceinline__ void fma2(u64& d, u64 a, u64 b) {
    asm("fma.rn.f32x2 %0,%1,%2,%0;" : "+l"(d) : "l"(a), "l"(b));
}
__device__ __forceinline__ float2 up2(u64 x) {
    float2 r; asm("mov.b64 {%0,%1}, %2;" : "=f"(r.x), "=f"(r.y) : "l"(x)); return r;
}

// ---------------- scratch ----------------
__device__ float g_norm[4][BB][LL];
__device__ float g_wnorm[4][4][BB][PP][LL];
__device__ __align__(16) float g_att[8][BB][LL][HH];
__device__ __align__(16) float g_cos[2][BB][LL][LL];   // [dir][b][i][j]
__device__ int   g_last[2][BB];
__device__ __align__(16) float g_hp[2][BB][16][LL][2*PP];

// ---------------- K1: norms (+ last indices) ----------------
__global__ void __launch_bounds__(128) k1_norms(const float* __restrict__ cp,
                                                const float* __restrict__ ch,
                                                const float* __restrict__ params,
                                                const int* __restrict__ mp,
                                                const int* __restrict__ mh)
{
    int b = blockIdx.y, i0 = blockIdx.x * 8, tid = threadIdx.x;
    __shared__ float vsq[8][4][HH];
    for (int t = tid; t < 8 * 2 * H2; t += 128) {
        int a = t / (2 * H2);
        int rem = t % (2 * H2);
        float v;
        if (rem < H2) v = cp[((size_t)b*LL + i0 + a)*H2 + rem];
        else          v = ch[((size_t)b*LL + i0 + a)*H2 + rem - H2];
        vsq[a][rem / HH][rem % HH] = v * v;
    }
    __syncthreads();
    if (tid < 32) {
        int a = tid >> 2, r = tid & 3;
        float s = 0.f;
        for (int h = 0; h < HH; h++) s += vsq[a][r][h];
        g_norm[r][b][i0 + a] = sqrtf(s);
    }
    for (int t = tid; t < 4 * 4 * PP; t += 128) {
        int r = t / (4 * PP);
        int rem = t % (4 * PP);
        int ml = rem / PP, p = rem % PP;
        int m = (r & 1) ? (2 * ml + 1) : (2 * ml);
        const float* w = params + (m * PP + p) * HH;
        float s[8] = {0,0,0,0,0,0,0,0};
        for (int h = 0; h < HH; h++) {
            float wv = w[h]; float w2 = wv * wv;
            #pragma unroll
            for (int a = 0; a < 8; a++) s[a] += w2 * vsq[a][r][h];
        }
        #pragma unroll
        for (int a = 0; a < 8; a++) g_wnorm[r][ml][b][p][i0 + a] = sqrtf(s[a]);
    }
    if (blockIdx.x == 0 && blockIdx.y == 0 && tid < BB) {
        int lp = 0, lh = 0;
        for (int j = 0; j < LL; j++) { lp += mp[tid*LL + j]; lh += mh[tid*LL + j]; }
        g_last[0][tid] = max(lp - 1, 0);
        g_last[1][tid] = max(lh - 1, 0);
    }
}

// ---------------- K23: cos + row stats + attentive h (4 anchors/block) ----------------
__global__ void __launch_bounds__(256) k23_rows(const float* __restrict__ cp,
                                                const float* __restrict__ ch,
                                                float* __restrict__ outp)
{
    __shared__ __align__(16) float pan[4 * H2];
    __shared__ float cosr[2 * 4 * LL];
    __shared__ float stat[2 * 4 * 2];

    int b = blockIdx.y, i0 = blockIdx.x * 4, tid = threadIdx.x;

    const float4* psrc = (const float4*)(cp + ((size_t)b*LL + i0)*H2);
    float4* pdst = (float4*)pan;
    for (int t = tid; t < 4 * 50; t += 256) pdst[t] = psrc[t];
    __syncthreads();

    int dir = tid >> 7, j = tid & 127;
    {
        const float4* tr = (const float4*)(ch + ((size_t)b*LL + j)*H2 + dir*HH);
        float nj = g_norm[2 + dir][b][j];
        float dacc[4] = {0,0,0,0};
        const float4* pb = (const float4*)(pan + dir*HH);
        #pragma unroll 5
        for (int c = 0; c < 25; c++) {
            float4 v = tr[c];
            #pragma unroll
            for (int a = 0; a < 4; a++) {
                float4 w = pb[a*50 + c];
                dacc[a] += v.x*w.x + v.y*w.y + v.z*w.z + v.w*w.w;
            }
        }
        #pragma unroll
        for (int a = 0; a < 4; a++) {
            float ni = g_norm[dir][b][i0 + a];
            float cv = dacc[a] / fmaxf(ni * nj, EPSF);
            cosr[(dir*4 + a)*128 + j] = cv;
            g_cos[dir][b][i0 + a][j] = cv;
        }
    }
    __syncthreads();

    int w = tid >> 5, lane = tid & 31;
    {   // 8 warps, 8 tasks
        int d = w >> 2, a = w & 3;
        float mx = -INFINITY, s = 0.f;
        for (int jj = lane; jj < 128; jj += 32) {
            float v = cosr[(d*4 + a)*128 + jj];
            mx = fmaxf(mx, v); s += v;
        }
        #pragma unroll
        for (int o = 16; o; o >>= 1) {
            mx = fmaxf(mx, __shfl_xor_sync(0xffffffffu, mx, o));
            s += __shfl_xor_sync(0xffffffffu, s, o);
        }
        if (lane == 0) { stat[(d*4 + a)*2] = mx; stat[(d*4 + a)*2 + 1] = s; }
    }
    __syncthreads();

    if (tid < 4) {
        float* o = outp + ((size_t)b*LL + i0 + tid)*CC;
        o[0] = stat[tid*2];         o[1] = stat[tid*2 + 1] * (1.f/LL);
        o[2] = stat[(4+tid)*2];     o[3] = stat[(4+tid)*2 + 1] * (1.f/LL);
    }

    if (tid < 200) {
        int d = tid >= 100;
        float inv[4], smv[4], mxv[4];
        #pragma unroll
        for (int a = 0; a < 4; a++) {
            inv[a] = 1.f / fmaxf(stat[(d*4 + a)*2 + 1], EPSF);
            smv[a] = 0.f; mxv[a] = -INFINITY;
        }
        const float* crow = cosr + d*4*128;
        const float* gb = ch + (size_t)b*LL*H2 + tid;
        for (int jj = 0; jj < 128; jj += 2) {
            float hv0 = gb[(size_t)jj*H2];
            float hv1 = gb[(size_t)(jj+1)*H2];
            #pragma unroll
            for (int a = 0; a < 4; a++) {
                float2 c2 = *(const float2*)&crow[a*128 + jj];
                float v0 = c2.x * hv0, v1 = c2.y * hv1;
                smv[a] += v0; smv[a] += v1;
                mxv[a] = fmaxf(mxv[a], fmaxf(v0, v1));
            }
        }
        int h = d ? tid - 100 : tid;
        for (int a = 0; a < 4; a++) {
            g_att[d ? 1 : 0][b][i0 + a][h] = smv[a] * inv[a];
            g_att[d ? 5 : 4][b][i0 + a][h] = mxv[a];
        }
    }
}

// ---------------- K4: col stats + attentive p (4 j-anchors/block) ----------------
__global__ void __launch_bounds__(256) k4_cols(const float* __restrict__ cp,
                                               float* __restrict__ outh)
{
    __shared__ float cosc[2 * 4 * LL];
    __shared__ float stat[2 * 4 * 2];

    int b = blockIdx.y, j0 = blockIdx.x * 4, tid = threadIdx.x;

    {   // 256 tasks: d in 0..1, i in 0..127
        int d = tid >> 7, i = tid & 127;
        float4 v = *(const float4*)&g_cos[d][b][i][j0];
        cosc[(d*4 + 0)*128 + i] = v.x;
        cosc[(d*4 + 1)*128 + i] = v.y;
        cosc[(d*4 + 2)*128 + i] = v.z;
        cosc[(d*4 + 3)*128 + i] = v.w;
    }
    __syncthreads();

    int w = tid >> 5, lane = tid & 31;
    {
        float mx = -INFINITY, s = 0.f;
        for (int ii = lane; ii < 128; ii += 32) {
            float v = cosc[w*128 + ii];
            mx = fmaxf(mx, v); s += v;
        }
        #pragma unroll
        for (int o = 16; o; o >>= 1) {
            mx = fmaxf(mx, __shfl_xor_sync(0xffffffffu, mx, o));
            s += __shfl_xor_sync(0xffffffffu, s, o);
        }
        if (lane == 0) { stat[w*2] = mx; stat[w*2 + 1] = s; }
    }
    __syncthreads();

    if (tid < 4) {
        float* o = outh + ((size_t)b*LL + j0 + tid)*CC;
        o[0] = stat[tid*2];         o[1] = stat[tid*2 + 1] * (1.f/LL);
        o[2] = stat[(4+tid)*2];     o[3] = stat[(4+tid)*2 + 1] * (1.f/LL);
    }

    if (tid < 200) {
        int d = tid >= 100;
        float inv[4], smv[4], mxv[4];
        #pragma unroll
        for (int a = 0; a < 4; a++) {
            inv[a] = 1.f / fmaxf(stat[(d*4 + a)*2 + 1], EPSF);
            smv[a] = 0.f; mxv[a] = -INFINITY;
        }
        const float* crow = cosc + d*4*128;
        const float* gb = cp + (size_t)b*LL*H2 + tid;
        for (int ii = 0; ii < 128; ii += 2) {
            float pv0 = gb[(size_t)ii*H2];
            float pv1 = gb[(size_t)(ii+1)*H2];
            #pragma unroll
            for (int a = 0; a < 4; a++) {
                float2 c2 = *(const float2*)&crow[a*128 + ii];
                float v0 = c2.x * pv0, v1 = c2.y * pv1;
                smv[a] += v0; smv[a] += v1;
                mxv[a] = fmaxf(mxv[a], fmaxf(v0, v1));
            }
        }
        int h = d ? tid - 100 : tid;
        for (int a = 0; a < 4; a++) {
            g_att[2 + d][b][j0 + a][h] = smv[a] * inv[a];
            g_att[6 + d][b][j0 + a][h] = mxv[a];
        }
    }
}

// ---------------- K5: vector-mpm groups (side as arg) ----------------
__global__ void __launch_bounds__(128) k5_vec(const float* __restrict__ cp,
                                              const float* __restrict__ ch,
                                              const float* __restrict__ params,
                                              float* __restrict__ out,
                                              int side)
{
    int b = blockIdx.y, i0 = blockIdx.x * 4, tid = threadIdx.x;
    __shared__ __align__(16) float v1s[4][2][HH];
    __shared__ __align__(16) float v2f[2][HH];
    __shared__ __align__(16) float v2a[4][4][HH];
    const float* base1 = side == 0 ? cp : ch;
    const float* other = side == 0 ? ch : cp;
    for (int t = tid; t < 4 * H2; t += 128) {
        int a = t / H2, rem = t % H2;
        v1s[a][rem / HH][rem % HH] = base1[((size_t)b*LL + i0 + a)*H2 + rem];
    }
    int lastIdx = g_last[side == 0 ? 1 : 0][b];
    for (int t = tid; t < H2; t += 128) {
        if (t < HH) v2f[0][t] = other[((size_t)b*LL + lastIdx)*H2 + t];
        else        v2f[1][t - HH] = other[(size_t)b*LL*H2 + t];
    }
    int a0 = side == 0 ? 0 : 2, a4 = side == 0 ? 4 : 6;
    for (int t = tid; t < 4 * 4 * HH; t += 128) {
        int a = t / (4 * HH);
        int g = (t / HH) % 4;
        int h = t % HH;
        int att = (g < 2) ? (a0 + g) : (a4 + g - 2);
        v2a[a][g][h] = g_att[att][b][i0 + a][h];
    }
    __syncthreads();
    if (tid < 120) {
        int g = tid / PP, p = tid % PP;
        const int mtab[6] = {0, 1, 4, 5, 6, 7};
        const int btab[6] = {4, 25, 126, 147, 168, 189};
        int m = mtab[g], dir = g & 1, base = btab[g];
        int rowset = side * 2 + dir;
        const float4* w4 = (const float4*)(params + (m * PP + p) * HH);
        bool p0 = (p == 0);

        const float4* v14[4];
        const float4* v24[4];
        #pragma unroll
        for (int a = 0; a < 4; a++) {
            v14[a] = (const float4*)v1s[a][dir];
            v24[a] = (g == 0) ? (const float4*)v2f[0]
                   : (g == 1) ? (const float4*)v2f[1]
                              : (const float4*)v2a[a][g - 2];
        }

        float s12[4] = {0,0,0,0}, s22[4] = {0,0,0,0};
        float dd[4]  = {0,0,0,0}, qq[4]  = {0,0,0,0};

        #pragma unroll 5
        for (int c = 0; c < 25; c++) {
            float4 w = w4[c];
            float w2x = w.x*w.x, w2y = w.y*w.y, w2z = w.z*w.z, w2w = w.w*w.w;
            #pragma unroll
            for (int a = 0; a < 4; a++) {
                float4 x = v24[a][c], v1 = v14[a][c];
                s12[a] += w2x*v1.x*x.x + w2y*v1.y*x.y + w2z*v1.z*x.z + w2w*v1.w*x.w;
                s22[a] += w2x*x.x*x.x  + w2y*x.y*x.y  + w2z*x.z*x.z  + w2w*x.w*x.w;
                if (p0) {
                    dd[a] += v1.x*x.x + v1.y*x.y + v1.z*x.z + v1.w*x.w;
                    qq[a] += x.x*x.x + x.y*x.y + x.z*x.z + x.w*x.w;
                }
            }
        }

        #pragma unroll
        for (int a = 0; a < 4; a++) {
            float n1 = g_wnorm[rowset][m >> 1][b][p][i0 + a];
            float val = s12[a] / (fmaxf(n1, EPSF) * fmaxf(sqrtf(s22[a]), EPSF));
            float* o = out + ((size_t)side*BB*LL + (size_t)b*LL + i0 + a)*CC;
            o[base + 1 + p] = val;
            if (p0) {
                float pn = g_norm[rowset][b][i0 + a];
                o[base] = dd[a] / (fmaxf(pn, EPSF) * fmaxf(sqrtf(qq[a]), EPSF));
            }
        }
    }
}

// ---------------- K6: fused pairwise mpm (transposed tile, 4-anchor/10-p blocking) ----
// dyn smem floats: t2 12800 @0 | w2 2000 @12800 | an 800 @14800 | invA 160 @15600 |
//   invT 128*21 @15760 | red 128*41 @18448 | part 320 @23696  -> 24016 floats (96064 B)
__global__ void __launch_bounds__(128) k6_pairwise(const float* __restrict__ cp,
                                                   const float* __restrict__ ch,
                                                   const float* __restrict__ params,
                                                   float* __restrict__ outp)
{
    extern __shared__ float sm[];
    u64*   t2   = (u64*)sm;                 // [50][128]
    float* w2f  = sm + 12800;               // [20][100]
    float* anf  = sm + 14800;               // [8][100]
    float* invA = sm + 15600;               // [8][20]
    float* invT = sm + 15760;               // [128][21]
    float* red  = sm + 18448;               // [128][41]
    float* part = sm + 23696;               // [160][2]
    const u64* w2 = (const u64*)w2f;        // [20][50]
    const u64* an = (const u64*)anf;        // [8][50]

    int tid = threadIdx.x;
    int b = blockIdx.y;
    int dir = blockIdx.z;
    int ib = blockIdx.x;
    int i0 = ib * 8;
    int m = 2 + dir;

    for (int t = tid; t < PP * HH; t += 128) {
        float wv = params[m * PP * HH + t];
        w2f[t] = wv * wv;
    }
    {
        const float* abase = cp + ((size_t)b*LL + i0)*H2 + dir*HH;
        for (int t = tid; t < 8 * 25; t += 128) {
            int a = t / 25, c = t % 25;
            *(float4*)(anf + a*HH + 4*c) = *(const float4*)(abase + (size_t)a*H2 + 4*c);
        }
    }
    {
        const float* tbase = ch + (size_t)b*LL*H2 + dir*HH;
        for (int t = tid; t < 128 * 25; t += 128) {
            int j = t / 25, c = t % 25;
            float4 v = *(const float4*)(tbase + (size_t)j*H2 + 4*c);
            *(float2*)&t2[(2*c)*128 + j]   = make_float2(v.x, v.y);
            *(float2*)&t2[(2*c+1)*128 + j] = make_float2(v.z, v.w);
        }
    }
    for (int t = tid; t < 8 * PP; t += 128) {
        int a = t / PP, p = t % PP;
        invA[a*PP + p] = 1.f / fmaxf(g_wnorm[dir][1][b][p][i0 + a], EPSF);
    }
    #pragma unroll
    for (int p = 0; p < PP; p++)
        invT[tid*21 + p] = 1.f / fmaxf(g_wnorm[2 + dir][1][b][p][tid], EPSF);
    __syncthreads();

    float hm[PP], hs[PP];
    #pragma unroll
    for (int p = 0; p < PP; p++) { hm[p] = -INFINITY; hs[p] = 0.f; }

    int jj = tid;
    for (int apass = 0; apass < 2; apass++) {
        int a0 = apass * 4;
        for (int ph = 0; ph < 2; ph++) {
            int pbase = ph * 10;
            u64 acc[4][10];
            #pragma unroll
            for (int a = 0; a < 4; a++)
                #pragma unroll
                for (int p = 0; p < 10; p++) acc[a][p] = 0ull;

            #pragma unroll 5
            for (int c = 0; c < 25; c++) {
                u64 v0 = t2[(2*c)*128 + jj];
                u64 v1 = t2[(2*c+1)*128 + jj];
                u64 pr0[4], pr1[4];
                #pragma unroll
                for (int a = 0; a < 4; a++) {
                    ulonglong2 aa = *(const ulonglong2*)&an[(a0 + a)*50 + 2*c];
                    pr0[a] = mul2(v0, aa.x);
                    pr1[a] = mul2(v1, aa.y);
                }
                #pragma unroll
                for (int p = 0; p < 10; p++) {
                    ulonglong2 w = *(const ulonglong2*)&w2[(pbase + p)*50 + 2*c];
                    #pragma unroll
                    for (int a = 0; a < 4; a++) {
                        fma2(acc[a][p], w.x, pr0[a]);
                        fma2(acc[a][p], w.y, pr1[a]);
                    }
                }
            }

            #pragma unroll
            for (int a = 0; a < 4; a++)
                #pragma unroll
                for (int p = 0; p < 10; p++) {
                    float2 x = up2(acc[a][p]);
                    float s = x.x + x.y;
                    float v = s * invA[(a0 + a)*PP + pbase + p] * invT[jj*21 + pbase + p];
                    red[jj*41 + a*10 + p] = v;
                    hm[pbase + p] = fmaxf(hm[pbase + p], v);
                    hs[pbase + p] += v;
                }
            __syncthreads();

            for (int t = tid; t < 160; t += 128) {
                int k = t >> 2, q = t & 3;
                float mx = -INFINITY, s = 0.f;
                int basej = q * 32;
                for (int r = 0; r < 32; r++) {
                    float v = red[(basej + r)*41 + k];
                    mx = fmaxf(mx, v); s += v;
                }
                part[t*2] = mx; part[t*2 + 1] = s;
            }
            __syncthreads();
            if (tid < 40) {
                int a = tid / 10, p = tid % 10;
                float mx = -INFINITY, s = 0.f;
                #pragma unroll
                for (int q = 0; q < 4; q++) {
                    int t = tid*4 + q;
                    mx = fmaxf(mx, part[t*2]);
                    s += part[t*2 + 1];
                }
                float* o = outp + ((size_t)b*LL + i0 + a0 + a)*CC;
                o[46 + dir*40 + pbase + p] = mx;
                o[66 + dir*40 + pbase + p] = s * (1.f/LL);
            }
            __syncthreads();
        }
    }

    float* gp = &g_hp[dir][b][ib][tid][0];
    #pragma unroll
    for (int p = 0; p < PP; p++) {
        gp[2*p]     = hm[p];
        gp[2*p + 1] = hs[p];
    }
}

// ---------------- K7: reduce mv_h partials ----------------
__global__ void __launch_bounds__(128) k7_reduce(float* __restrict__ out)
{
    int b = blockIdx.x, dir = blockIdx.y, j = threadIdx.x;
    float* o = out + (size_t)BB*LL*CC + ((size_t)b*LL + j)*CC;
    for (int p = 0; p < PP; p++) {
        float mx = -INFINITY, s = 0.f;
        #pragma unroll
        for (int ib = 0; ib < 16; ib++) {
            float2 v = *(const float2*)&g_hp[dir][b][ib][j][2*p];
            mx = fmaxf(mx, v.x); s += v.y;
        }
        o[46 + dir*40 + p] = mx;
        o[66 + dir*40 + p] = s * (1.f/LL);
    }
}

// ---------------- launch ----------------
extern "C" void kernel_launch(void* const* d_in, const int* in_sizes, int n_in,
                              void* d_out, int out_size)
{
    const float* cp     = (const float*)d_in[0];
    const int*   mp     = (const int*)d_in[1];
    const float* ch     = (const float*)d_in[2];
    const int*   mh     = (const int*)d_in[3];
    const float* params = (const float*)d_in[4];
    float* out = (float*)d_out;
    float* out_h = out + (size_t)BB*LL*CC;

    static cudaStream_t s1 = 0, s2 = 0;
    static cudaEvent_t evA = 0, evB = 0, evJ1 = 0, evJ2 = 0;
    static int init_done = 0;
    if (!init_done) {
        cudaFuncSetAttribute(k6_pairwise, cudaFuncAttributeMaxDynamicSharedMemorySize, 96064);
        cudaStreamCreateWithFlags(&s1, cudaStreamNonBlocking);
        cudaStreamCreateWithFlags(&s2, cudaStreamNonBlocking);
        cudaEventCreateWithFlags(&evA,  cudaEventDisableTiming);
        cudaEventCreateWithFlags(&evB,  cudaEventDisableTiming);
        cudaEventCreateWithFlags(&evJ1, cudaEventDisableTiming);
        cudaEventCreateWithFlags(&evJ2, cudaEventDisableTiming);
        init_done = 1;
    }

    // k1 on main stream, then fork
    k1_norms<<<dim3(LL/8, BB), 128>>>(cp, ch, params, mp, mh);
    cudaEventRecord(evA, 0);
    cudaStreamWaitEvent(s1, evA, 0);

    // branch 1: k6 -> k7 (needs only k1)
    k6_pairwise<<<dim3(LL/8, BB, 2), 128, 96064, s1>>>(cp, ch, params, out);
    k7_reduce<<<dim3(BB, 2), 128, 0, s1>>>(out);
    cudaEventRecord(evJ1, s1);

    // main: k23, then fork k5 side0 (needs only k23's att)
    k23_rows<<<dim3(LL/4, BB), 256>>>(cp, ch, out);
    cudaEventRecord(evB, 0);
    cudaStreamWaitEvent(s2, evB, 0);
    k5_vec<<<dim3(LL/4, BB), 128, 0, s2>>>(cp, ch, params, out, 0);
    cudaEventRecord(evJ2, s2);

    // main: k4 -> k5 side1
    k4_cols<<<dim3(LL/4, BB), 256>>>(cp, out_h);
    k5_vec<<<dim3(LL/4, BB), 128>>>(cp, ch, params, out, 1);

    // join
    cudaStreamWaitEvent(0, evJ1, 0);
    cudaStreamWaitEvent(0, evJ2, 0);
}